// round 14
// baseline (speedup 1.0000x reference)
#include <cuda_runtime.h>
#include <cuda_bf16.h>
#include <cstdint>

// Problem constants
#define NUM_CITIES 50000
#define EMB 50
#define HID 64
#define G4 256          // 4*HID
#define BATCH 1024
#define SEQ 512
#define BR 8            // batch rows per LSTM block
#define NT 256          // threads per block

typedef unsigned long long ull;

// ---------------- scratch (static __device__ globals; no allocation) ----------
__device__ float g_ht[HID * BATCH];           // final hidden, transposed [k][m]
__device__ float g_Wt[HID * NUM_CITIES];      // W_fc transposed [k][n]  (12.8 MB)
__device__ float g_inv[BATCH];                // 1 / rowsum(exp(logits))

// ---------------- packed f32x2 helpers ---------------------------------------
__device__ __forceinline__ ull pack2(float x, float y) {
    ull r; asm("mov.b64 %0, {%1, %2};" : "=l"(r) : "f"(x), "f"(y)); return r;
}
__device__ __forceinline__ ull fma2(ull a, ull b, ull c) {
    ull d; asm("fma.rn.f32x2 %0, %1, %2, %3;" : "=l"(d) : "l"(a), "l"(b), "l"(c)); return d;
}
__device__ __forceinline__ float2 unpack2(ull v) {
    float2 f; asm("mov.b64 {%0, %1}, %2;" : "=f"(f.x), "=f"(f.y) : "l"(v)); return f;
}
__device__ __forceinline__ float sigmoidf_(float v) {
    return __fdividef(1.0f, 1.0f + __expf(-v));
}

// ---------------- K0: transpose W_fc [N,64] -> g_Wt [64,N] --------------------
__global__ void transpose_wfc_kernel(const float* __restrict__ W_fc) {
    __shared__ float t[32][33];
    int n0 = blockIdx.x * 32, k0 = blockIdx.y * 32;
    int n = n0 + threadIdx.y, k = k0 + threadIdx.x;
    if (n < NUM_CITIES) t[threadIdx.y][threadIdx.x] = W_fc[(size_t)n * HID + k];
    __syncthreads();
    int kk = k0 + threadIdx.y, nn = n0 + threadIdx.x;
    if (nn < NUM_CITIES) g_Wt[(size_t)kk * NUM_CITIES + nn] = t[threadIdx.x][threadIdx.y];
}

// ---------------- K1: fused embedding + LSTM (persistent, 8 rows / block) -----
__global__ void __launch_bounds__(NT, 1) lstm_kernel(
    const int*   __restrict__ x,
    const float* __restrict__ emb,
    const float* __restrict__ W_ih,
    const float* __restrict__ W_hh,
    const float* __restrict__ b_ih,
    const float* __restrict__ b_hh)
{
    __shared__ int   x_sh[BR][SEQ];                      // 16 KB
    __shared__ __align__(16) float e_sh[2][EMB][BR];     // 3.2 KB  [buf][k][r]
    __shared__ __align__(16) float h_sh[HID][BR];        // 2 KB    [k][r]
    __shared__ float c_sh[BR][HID];                      // 2 KB    [r][j]
    __shared__ float gates_sh[BR][G4];                   // 8 KB    [r][g]

    const int tid  = threadIdx.x;
    const int g    = tid;                                // this thread's gate row
    const int row0 = blockIdx.x * BR;

    // load this block's x rows
    for (int i = tid; i < BR * SEQ; i += NT) {
        int r = i >> 9, s = i & 511;
        x_sh[r][s] = x[(size_t)(row0 + r) * SEQ + s];
    }
    // zero h, c
    for (int i = tid; i < BR * HID; i += NT) {
        ((float*)h_sh)[i] = 0.0f;
        ((float*)c_sh)[i] = 0.0f;
    }
    // gate-row weights in registers
    float wih[EMB], whh[HID];
#pragma unroll
    for (int k = 0; k < EMB; k++) wih[k] = W_ih[g * EMB + k];
#pragma unroll
    for (int k = 0; k < HID; k++) whh[k] = W_hh[g * HID + k];
    const float bias = b_ih[g] + b_hh[g];

    __syncthreads();
    // preload e(t=0): 400 elements
    for (int i = tid; i < BR * EMB; i += NT) {
        int r = i / EMB, k = i % EMB;
        e_sh[0][k][r] = emb[(size_t)x_sh[r][0] * EMB + k];
    }
    __syncthreads();

    const bool is_tanh_gate = (g >= 2 * HID) && (g < 3 * HID);  // warp-uniform

    int cur = 0;
    for (int t = 0; t < SEQ; ++t) {
        // prefetch e(t+1) into registers (latency hidden behind dot products)
        float pf0 = 0.0f, pf1 = 0.0f;
        const bool haspf = (t + 1 < SEQ);
        if (haspf) {
            { int r = tid / EMB, k = tid % EMB;
              pf0 = emb[(size_t)x_sh[r][t + 1] * EMB + k]; }
            if (tid < BR * EMB - NT) {
                int i1 = tid + NT; int r = i1 / EMB, k = i1 % EMB;
                pf1 = emb[(size_t)x_sh[r][t + 1] * EMB + k];
            }
        }

        // gate dot products for 8 rows as 4 packed row-pairs
        ull acc0, acc1, acc2, acc3;
        acc0 = acc1 = acc2 = acc3 = pack2(bias, bias);
#pragma unroll
        for (int k = 0; k < EMB; k++) {
            ull w2 = pack2(wih[k], wih[k]);
            ulonglong2 eA = *(const ulonglong2*)&e_sh[cur][k][0];
            ulonglong2 eB = *(const ulonglong2*)&e_sh[cur][k][4];
            acc0 = fma2(w2, eA.x, acc0);
            acc1 = fma2(w2, eA.y, acc1);
            acc2 = fma2(w2, eB.x, acc2);
            acc3 = fma2(w2, eB.y, acc3);
        }
#pragma unroll
        for (int k = 0; k < HID; k++) {
            ull w2 = pack2(whh[k], whh[k]);
            ulonglong2 hA = *(const ulonglong2*)&h_sh[k][0];
            ulonglong2 hB = *(const ulonglong2*)&h_sh[k][4];
            acc0 = fma2(w2, hA.x, acc0);
            acc1 = fma2(w2, hA.y, acc1);
            acc2 = fma2(w2, hB.x, acc2);
            acc3 = fma2(w2, hB.y, acc3);
        }

        // activations + store per-row gate values
        {
            float2 v0 = unpack2(acc0), v1 = unpack2(acc1);
            float2 v2 = unpack2(acc2), v3 = unpack2(acc3);
            if (is_tanh_gate) {
                gates_sh[0][g] = tanhf(v0.x); gates_sh[1][g] = tanhf(v0.y);
                gates_sh[2][g] = tanhf(v1.x); gates_sh[3][g] = tanhf(v1.y);
                gates_sh[4][g] = tanhf(v2.x); gates_sh[5][g] = tanhf(v2.y);
                gates_sh[6][g] = tanhf(v3.x); gates_sh[7][g] = tanhf(v3.y);
            } else {
                gates_sh[0][g] = sigmoidf_(v0.x); gates_sh[1][g] = sigmoidf_(v0.y);
                gates_sh[2][g] = sigmoidf_(v1.x); gates_sh[3][g] = sigmoidf_(v1.y);
                gates_sh[4][g] = sigmoidf_(v2.x); gates_sh[5][g] = sigmoidf_(v2.y);
                gates_sh[6][g] = sigmoidf_(v3.x); gates_sh[7][g] = sigmoidf_(v3.y);
            }
        }
        __syncthreads();   // gates ready; all reads of h_sh/e_sh[cur] done

        // stash prefetched e into the other buffer
        if (haspf) {
            { int r = tid / EMB, k = tid % EMB; e_sh[cur ^ 1][k][r] = pf0; }
            if (tid < BR * EMB - NT) {
                int i1 = tid + NT; int r = i1 / EMB, k = i1 % EMB;
                e_sh[cur ^ 1][k][r] = pf1;
            }
        }

        // c/h update: 512 (r,j) tasks, 2 per thread
#pragma unroll
        for (int q = 0; q < 2; q++) {
            int task = tid + q * NT;
            int r = task >> 6, j = task & 63;
            float iv = gates_sh[r][j];
            float fv = gates_sh[r][HID + j];
            float gv = gates_sh[r][2 * HID + j];
            float ov = gates_sh[r][3 * HID + j];
            float c = fv * c_sh[r][j] + iv * gv;
            c_sh[r][j] = c;
            h_sh[j][r] = ov * tanhf(c);
        }
        __syncthreads();
        cur ^= 1;
    }

    // write final hidden transposed: g_ht[j][m]
    for (int i = tid; i < BR * HID; i += NT) {
        int r = i >> 6, j = i & 63;
        g_ht[(size_t)j * BATCH + row0 + r] = h_sh[j][r];
    }
}

// ---------------- K2: logits = h @ W_fc^T + b_fc  (64x64 tiles, f32x2) --------
__global__ void __launch_bounds__(NT) logits_kernel(
    const float* __restrict__ b_fc, float* __restrict__ out)
{
    __shared__ __align__(16) float A_sh[HID][64];   // [k][m]
    __shared__ __align__(16) float B_sh[HID][64];   // [k][n]
    const int tid = threadIdx.x;
    const int m0 = blockIdx.y * 64;
    const int n0 = blockIdx.x * 64;

    for (int i = tid; i < 64 * 64; i += NT) {
        int k = i >> 6, m = i & 63;
        A_sh[k][m] = g_ht[(size_t)k * BATCH + m0 + m];
    }
    for (int i = tid; i < 64 * 64; i += NT) {
        int k = i >> 6, n = i & 63;
        int ng = n0 + n;
        B_sh[k][n] = (ng < NUM_CITIES) ? g_Wt[(size_t)k * NUM_CITIES + ng] : 0.0f;
    }
    __syncthreads();

    const int tx = tid & 15;   // col group (4 cols)
    const int ty = tid >> 4;   // row group (4 rows = 2 packed pairs)

    ull acc[2][4];
#pragma unroll
    for (int p = 0; p < 2; p++)
#pragma unroll
        for (int c = 0; c < 4; c++) acc[p][c] = 0ull;

#pragma unroll 16
    for (int k = 0; k < HID; k++) {
        ulonglong2 a2 = *(const ulonglong2*)&A_sh[k][ty * 4];   // row pairs
        float4 b4 = *(const float4*)&B_sh[k][tx * 4];
        ull b0 = pack2(b4.x, b4.x), b1 = pack2(b4.y, b4.y);
        ull b2 = pack2(b4.z, b4.z), b3 = pack2(b4.w, b4.w);
        acc[0][0] = fma2(a2.x, b0, acc[0][0]);
        acc[1][0] = fma2(a2.y, b0, acc[1][0]);
        acc[0][1] = fma2(a2.x, b1, acc[0][1]);
        acc[1][1] = fma2(a2.y, b1, acc[1][1]);
        acc[0][2] = fma2(a2.x, b2, acc[0][2]);
        acc[1][2] = fma2(a2.y, b2, acc[1][2]);
        acc[0][3] = fma2(a2.x, b3, acc[0][3]);
        acc[1][3] = fma2(a2.y, b3, acc[1][3]);
    }

    int ng = n0 + tx * 4;
    if (ng < NUM_CITIES) {   // NUM_CITIES % 4 == 0, so full float4 is in-bounds
        float4 bv = *(const float4*)&b_fc[ng];
#pragma unroll
        for (int p = 0; p < 2; p++) {
            int mg = m0 + ty * 4 + p * 2;
            float2 v0 = unpack2(acc[p][0]), v1 = unpack2(acc[p][1]);
            float2 v2 = unpack2(acc[p][2]), v3 = unpack2(acc[p][3]);
            float4 lo = make_float4(v0.x + bv.x, v1.x + bv.y, v2.x + bv.z, v3.x + bv.w);
            float4 hi = make_float4(v0.y + bv.x, v1.y + bv.y, v2.y + bv.z, v3.y + bv.w);
            *(float4*)&out[(size_t)mg * NUM_CITIES + ng] = lo;
            *(float4*)&out[(size_t)(mg + 1) * NUM_CITIES + ng] = hi;
        }
    }
}

// ---------------- K3: per-row sum of exp(logits) ------------------------------
__global__ void __launch_bounds__(NT) rowsum_kernel(const float* __restrict__ logits)
{
    const int row = blockIdx.x;
    const float4* p = (const float4*)(logits + (size_t)row * NUM_CITIES);
    float s = 0.0f;
    for (int i = threadIdx.x; i < NUM_CITIES / 4; i += NT) {
        float4 v = p[i];
        s += __expf(v.x) + __expf(v.y) + __expf(v.z) + __expf(v.w);
    }
    __shared__ float red[NT];
    red[threadIdx.x] = s;
    __syncthreads();
    for (int o = NT / 2; o > 0; o >>= 1) {
        if (threadIdx.x < o) red[threadIdx.x] += red[threadIdx.x + o];
        __syncthreads();
    }
    if (threadIdx.x == 0) g_inv[row] = 1.0f / red[0];
}

// ---------------- K4: out = exp(logits) * inv_rowsum --------------------------
__global__ void __launch_bounds__(NT) normalize_kernel(float* __restrict__ out)
{
    const int row = blockIdx.y;
    const int c = (blockIdx.x * NT + threadIdx.x) * 4;
    if (c < NUM_CITIES) {
        const float inv = g_inv[row];
        float4* p = (float4*)&out[(size_t)row * NUM_CITIES + c];
        float4 v = *p;
        v.x = __expf(v.x) * inv;
        v.y = __expf(v.y) * inv;
        v.z = __expf(v.z) * inv;
        v.w = __expf(v.w) * inv;
        *p = v;
    }
}

// ---------------- launch -------------------------------------------------------
extern "C" void kernel_launch(void* const* d_in, const int* in_sizes, int n_in,
                              void* d_out, int out_size)
{
    const int*   x    = (const int*)  d_in[0];   // [1024, 512]
    const float* emb  = (const float*)d_in[1];   // [50000, 50]
    const float* W_ih = (const float*)d_in[2];   // [256, 50]
    const float* W_hh = (const float*)d_in[3];   // [256, 64]
    const float* b_ih = (const float*)d_in[4];   // [256]
    const float* b_hh = (const float*)d_in[5];   // [256]
    const float* W_fc = (const float*)d_in[6];   // [50000, 64]
    const float* b_fc = (const float*)d_in[7];   // [50000]
    float* out = (float*)d_out;                  // [1024, 50000]

    transpose_wfc_kernel<<<dim3((NUM_CITIES + 31) / 32, HID / 32), dim3(32, 32)>>>(W_fc);
    lstm_kernel<<<BATCH / BR, NT>>>(x, emb, W_ih, W_hh, b_ih, b_hh);
    logits_kernel<<<dim3((NUM_CITIES + 63) / 64, BATCH / 64), NT>>>(b_fc, out);
    rowsum_kernel<<<BATCH, NT>>>(out);
    normalize_kernel<<<dim3((NUM_CITIES / 4 + NT - 1) / NT, BATCH), NT>>>(out);
}